// round 15
// baseline (speedup 1.0000x reference)
#include <cuda_runtime.h>
#include <math.h>

#define NT   256
#define BSUB 4
#define TT   128
#define DD   256
#define HW   128
#define NSTG 1016  // (TT-1)*2*4

typedef unsigned long long ull;

__device__ __forceinline__ float tanha(float x) {
    float y; asm("tanh.approx.f32 %0, %1;" : "=f"(y) : "f"(x)); return y;
}
#define FFMA2(acc, a, b) \
    asm("fma.rn.f32x2 %0, %1, %2, %3;" : "=l"(acc) : "l"(a), "l"(b), "l"(acc))
#define ADD2(d, a, b) \
    asm("add.rn.f32x2 %0, %1, %2;" : "=l"(d) : "l"(a), "l"(b))
#define PACK2(d, lo, hi) \
    asm("mov.b64 %0, {%1,%2};" : "=l"(d) : "f"(lo), "f"(hi))
#define UNPACK2(lo, hi, d) \
    asm("mov.b64 {%0,%1}, %2;" : "=f"(lo), "=f"(hi) : "l"(d))
#define BAR_SYNC(id)   asm volatile("bar.sync %0, 256;"   :: "r"(id) : "memory")
#define BAR_ARRIVE(id) asm volatile("bar.arrive %0, 256;" :: "r"(id) : "memory")

__device__ __forceinline__ float interp_c(float t, const float* __restrict__ row) {
    int i = (int)ceilf(t);
    i = i < 1 ? 1 : (i > DD - 1 ? DD - 1 : i);
    float w = t - (float)(i - 1);
    w = fminf(fmaxf(w, 0.f), 1.f);
    return (1.f - w) * row[i - 1] + w * row[i];
}

// L2 partial GEMM over a k-slice of 4*NQ columns, 4 o per thread, 4 rows.
// Stores packed (o, o+64) f32x2 partials: pSd[row][kg][slot], slot = l + 32*m'.
template<int NQ>
__device__ __forceinline__ void l2_slice(
    const ull (*w2p)[2 * NQ],
    const float* __restrict__ h1r, ull* __restrict__ pSd,
    int kg, int kbase, int l)
{
    #pragma unroll
    for (int half = 0; half < 2; ++half) {
        ull accA[4] = {0ull, 0ull, 0ull, 0ull};
        ull accB[4] = {0ull, 0ull, 0ull, 0ull};
        const float* ra = h1r + (2 * half) * HW + kbase;
        const float* rb = ra + HW;
        #pragma unroll
        for (int kq = 0; kq < NQ; ++kq) {
            ulonglong2 ha = *reinterpret_cast<const ulonglong2*>(ra + 4 * kq);
            ulonglong2 hb = *reinterpret_cast<const ulonglong2*>(rb + 4 * kq);
            #pragma unroll
            for (int m = 0; m < 4; ++m) {
                FFMA2(accA[m], w2p[m][2 * kq],     ha.x);
                FFMA2(accA[m], w2p[m][2 * kq + 1], ha.y);
                FFMA2(accB[m], w2p[m][2 * kq],     hb.x);
                FFMA2(accB[m], w2p[m][2 * kq + 1], hb.y);
            }
        }
        float sA[4], sB[4];
        #pragma unroll
        for (int m = 0; m < 4; ++m) {
            float lo, hi;
            UNPACK2(lo, hi, accA[m]); sA[m] = lo + hi;
            UNPACK2(lo, hi, accB[m]); sB[m] = lo + hi;
        }
        ull pA0, pA1, pB0, pB1;
        PACK2(pA0, sA[0], sA[2]);   // (o=l,    o=l+64)
        PACK2(pA1, sA[1], sA[3]);   // (o=l+32, o=l+96)
        PACK2(pB0, sB[0], sB[2]);
        PACK2(pB1, sB[1], sB[3]);
        const int rowA = 2 * half, rowB = 2 * half + 1;
        pSd[rowA * 512 + kg * 64 + l]      = pA0;
        pSd[rowA * 512 + kg * 64 + l + 32] = pA1;
        pSd[rowB * 512 + kg * 64 + l]      = pB0;
        pSd[rowB * 512 + kg * 64 + l + 32] = pB1;
    }
}

__global__ __launch_bounds__(NT, 2)
void ode_kernel(const float* __restrict__ ts, const float* __restrict__ y0,
                const float* __restrict__ latent, const int* __restrict__ length,
                const float* __restrict__ dts, const float* __restrict__ dcs,
                const float* __restrict__ W1, const float* __restrict__ b1,
                const float* __restrict__ W2, const float* __restrict__ b2,
                const float* __restrict__ W3, const float* __restrict__ b3,
                float* __restrict__ out)
{
    extern __shared__ float sm[];
    ull*    w1v  = reinterpret_cast<ull*>(sm);           // [32][34] u64
    float2* tmW  = reinterpret_cast<float2*>(sm + 2176); // [1024] (tt, wgt)
    ull*    pSd  = reinterpret_cast<ull*>(sm + 4224);    // [4 r][8 kg][64 slots]
    float*  ctab = sm + 8320;                            // [4 r][1024]
    float*  W3t  = sm + 12416;                           // [128][9]
    float*  h1r  = sm + 13568;                           // [4][128]
    float*  tmS  = sm + 14080;                           // [1024] stg
    ull*    b2d  = reinterpret_cast<ull*>(sm + 15104);   // [64] (b2[o], b2[o+64])
    ull*    kvS  = reinterpret_cast<ull*>(sm + 15232);   // [4 r][6] finished kv

    const int tid = threadIdx.x;
    const int l   = tid & 31;
    const int kg  = tid >> 5;
    const int r0  = blockIdx.x * BSUB;

    // ---- one-time setup ----
    for (int i = tid; i < 9 * HW; i += NT) {
        int oo = i >> 7, k = i & 127;
        W3t[k * 9 + oo] = W3[i];
    }
    for (int i = tid; i < 768; i += NT) {   // w1v[ll][nn][j]
        int ll = i / 24, rem = i % 24;
        int nn = rem / 6, j = rem % 6;
        int o = 4 * ll + nn;
        const float* w = W1 + o * 43;
        float lo = 0.f, hi = 0.f;
        if (j < 4)      { lo = w[2 * j]; hi = w[2 * j + 1]; }
        else if (j == 4){ lo = w[8];     hi = w[41]; }
        ull p; PACK2(p, lo, hi);
        w1v[ll * 34 + nn * 6 + j] = p;
    }
    for (int g = tid; g < NSTG; g += NT) {  // time tables
        int n = g >> 3, sub = (g >> 2) & 1, s = g & 3;
        float t0v = ts[n];
        float dtf = (ts[n + 1] - t0v) * 0.5f;
        float tstart = t0v + (sub ? dtf : 0.f);
        float As = (s == 0) ? 0.f : ((s == 3) ? 1.f : 0.5f);
        float tt = tstart + As * dtf;
        float wgt = dtf * (1.f / 6.f) * ((s == 0 || s == 3) ? 1.f : 2.f);
        tmW[g] = make_float2(tt, wgt);
        tmS[g] = ((s == 2) ? 1.f : 0.5f) * dtf;
    }
    for (int i = tid; i < 4096; i += NT) {  // concentration table
        int r = i >> 10, g = i & 1023;
        if (g < NSTG) {
            int n = g >> 3, sub = (g >> 2) & 1, s = g & 3;
            float t0v = ts[n];
            float dtf = (ts[n + 1] - t0v) * 0.5f;
            float tstart = t0v + (sub ? dtf : 0.f);
            float As = (s == 0) ? 0.f : ((s == 3) ? 1.f : 0.5f);
            float tt = tstart + As * dtf;
            ctab[i] = interp_c(tt, dcs + (r0 + r) * DD);
        }
    }
    for (int k = tid; k < 64; k += NT) {
        ull p; PACK2(p, b2[k], b2[k + 64]);
        b2d[k] = p;
    }

    if (kg < BSUB) {
        // ================= ROW WARP (row r = kg): L1 + small L2 + epilogue =================
        const int r = kg;
        ull w2p[4][6];                       // 12-k slice, kbase = 12*kg
        #pragma unroll
        for (int m = 0; m < 4; ++m) {
            const float* wr = W2 + (l + 32 * m) * HW + 12 * kg;
            #pragma unroll
            for (int kp = 0; kp < 6; ++kp) PACK2(w2p[m][kp], wr[2 * kp], wr[2 * kp + 1]);
        }
        ull wcbr[4];                         // (w_c, b1 + W1[:,9:41]·latent[r])
        #pragma unroll
        for (int nn = 0; nn < 4; ++nn) {
            int o = 4 * l + nn;
            const float* w = W1 + o * 43;
            float bp = b1[o];
            const float* lat = latent + (r0 + r) * 32;
            #pragma unroll
            for (int j = 0; j < 32; ++j) bp += w[9 + j] * lat[j];
            PACK2(wcbr[nn], w[42], bp);
        }
        ull ybase[4], yacc[4], ycur[4];
        #pragma unroll
        for (int j = 0; j < 4; ++j) { ybase[j] = 0ull; yacc[j] = 0ull; ycur[j] = 0ull; }
        float ybase8 = 0.f, yacc8 = 0.f, ycur8 = 0.f;
        float y0r = y0[r0 + r];
        if (l == 0) out[(r0 + r) * TT] = y0r;
        PACK2(ybase[0], y0r, 0.f);
        yacc[0] = ybase[0];
        ycur[0] = ybase[0];
        __syncthreads();

        #pragma unroll 1
        for (int g = 0; g < NSTG; ++g) {
            // ---- layer 1 (uses ycur computed at end of previous stage) ----
            {
                float c = ctab[(r << 10) + g];
                float tt = tmW[g].x;
                ull ytt, c1;
                PACK2(ytt, ycur8, tt);
                PACK2(c1, c, 1.0f);
                float hq[4];
                #pragma unroll
                for (int nn = 0; nn < 4; ++nn) {
                    const ull* wb = w1v + l * 34 + nn * 6;
                    ulonglong2 A = *reinterpret_cast<const ulonglong2*>(wb);
                    ulonglong2 B = *reinterpret_cast<const ulonglong2*>(wb + 2);
                    ulonglong2 C = *reinterpret_cast<const ulonglong2*>(wb + 4);
                    ull acc = 0ull;
                    FFMA2(acc, A.x, ycur[0]);
                    FFMA2(acc, A.y, ycur[1]);
                    FFMA2(acc, B.x, ycur[2]);
                    FFMA2(acc, B.y, ycur[3]);
                    FFMA2(acc, C.x, ytt);
                    FFMA2(acc, wcbr[nn], c1);
                    float lo, hi; UNPACK2(lo, hi, acc);
                    hq[nn] = tanha(lo + hi);
                }
                *reinterpret_cast<float4*>(h1r + r * HW + 4 * l) =
                    make_float4(hq[0], hq[1], hq[2], hq[3]);
            }
            BAR_SYNC(0);                       // h1 ready (all warps)

            l2_slice<3>(w2p, h1r, pSd, kg, 12 * kg, l);
            BAR_ARRIVE(1);                     // helpers wait for our pS
            BAR_SYNC(3);                       // wait for helpers' finished kv

            // ---- epilogue: broadcast-load finished kv, update state ----
            {
                const ull* kr = kvS + r * 6;
                ulonglong2 q0 = *reinterpret_cast<const ulonglong2*>(kr);
                ulonglong2 q1 = *reinterpret_cast<const ulonglong2*>(kr + 2);
                ull p0 = q0.x, p1 = q0.y, p2 = q1.x, p3 = q1.y;
                float a8 = reinterpret_cast<const float*>(kr + 4)[0];
                float wgt = tmW[g].y;
                ull wg2; PACK2(wg2, wgt, wgt);
                FFMA2(yacc[0], wg2, p0);
                FFMA2(yacc[1], wg2, p1);
                FFMA2(yacc[2], wg2, p2);
                FFMA2(yacc[3], wg2, p3);
                yacc8 = fmaf(wgt, a8, yacc8);
                if ((g & 3) != 3) {
                    float stg = tmS[g];
                    ull st2; PACK2(st2, stg, stg);
                    ycur[0] = ybase[0]; FFMA2(ycur[0], st2, p0);
                    ycur[1] = ybase[1]; FFMA2(ycur[1], st2, p1);
                    ycur[2] = ybase[2]; FFMA2(ycur[2], st2, p2);
                    ycur[3] = ybase[3]; FFMA2(ycur[3], st2, p3);
                    ycur8 = fmaf(stg, a8, ybase8);
                } else {
                    #pragma unroll
                    for (int j = 0; j < 4; ++j) { ybase[j] = yacc[j]; ycur[j] = yacc[j]; }
                    ybase8 = yacc8; ycur8 = yacc8;
                    if ((g & 7) == 7 && l == 0) {
                        float yb, dum; UNPACK2(yb, dum, ybase[0]);
                        out[(r0 + r) * TT + (g >> 3) + 1] = yb;
                    }
                }
            }
        }
    } else {
        // ================= HELPER WARP (kg 4..7): big L2 + full L3 for row kg-4 =================
        const int r = kg - 4;
        const int kbase = 48 + 20 * (kg - 4);
        ull w2p[4][10];
        #pragma unroll
        for (int m = 0; m < 4; ++m) {
            const float* wr = W2 + (l + 32 * m) * HW + kbase;
            #pragma unroll
            for (int kp = 0; kp < 10; ++kp) PACK2(w2p[m][kp], wr[2 * kp], wr[2 * kp + 1]);
        }
        ull b3p[4];
        #pragma unroll
        for (int j = 0; j < 4; ++j) PACK2(b3p[j], b3[2 * j], b3[2 * j + 1]);
        const float b3_8 = b3[8];
        int len = length[r0 + r];
        int idx = len - 1; if (idx < 0) idx = 0;
        const float tendr = ts[idx];
        __syncthreads();

        #pragma unroll 1
        for (int g = 0; g < NSTG; ++g) {
            BAR_SYNC(0);                       // wait for h1
            l2_slice<5>(w2p, h1r, pSd, kg, kbase, l);
            BAR_SYNC(1);                       // wait for ALL pS (incl. row warps')

            // ---- full layer 3 for row r ----
            float acc9[9];
            #pragma unroll
            for (int o2 = 0; o2 < 9; ++o2) acc9[o2] = 0.f;
            #pragma unroll
            for (int jj = 0; jj < 2; ++jj) {
                const int slot = l + 32 * jj;
                const ull* pb = pSd + r * 512 + slot;
                ull t0v, t1v, t2v, t3v;
                ADD2(t0v, pb[0],   pb[64]);
                ADD2(t1v, pb[128], pb[192]);
                ADD2(t2v, pb[256], pb[320]);
                ADD2(t3v, pb[384], pb[448]);
                ADD2(t0v, t0v, t1v);
                ADD2(t2v, t2v, t3v);
                ADD2(t0v, t0v, t2v);
                ADD2(t0v, t0v, b2d[slot]);
                float lo, hi; UNPACK2(lo, hi, t0v);
                float hA = tanha(lo);          // o = slot
                float hB = tanha(hi);          // o = slot + 64
                const float* wA = W3t + slot * 9;
                const float* wB = W3t + (slot + 64) * 9;
                #pragma unroll
                for (int o2 = 0; o2 < 9; ++o2)
                    acc9[o2] += hA * wA[o2] + hB * wB[o2];
            }
            ull p0, p1, p2, p3;
            PACK2(p0, acc9[0], acc9[1]);
            PACK2(p1, acc9[2], acc9[3]);
            PACK2(p2, acc9[4], acc9[5]);
            PACK2(p3, acc9[6], acc9[7]);
            float a8 = acc9[8];
            #pragma unroll
            for (int off = 16; off > 0; off >>= 1) {
                ull s0 = __shfl_xor_sync(0xffffffffu, p0, off);
                ull s1 = __shfl_xor_sync(0xffffffffu, p1, off);
                ull s2 = __shfl_xor_sync(0xffffffffu, p2, off);
                ull s3 = __shfl_xor_sync(0xffffffffu, p3, off);
                a8 += __shfl_xor_sync(0xffffffffu, a8, off);
                ADD2(p0, p0, s0);
                ADD2(p1, p1, s1);
                ADD2(p2, p2, s2);
                ADD2(p3, p3, s3);
            }
            ADD2(p0, p0, b3p[0]);
            ADD2(p1, p1, b3p[1]);
            ADD2(p2, p2, b3p[2]);
            ADD2(p3, p3, b3p[3]);
            a8 += b3_8;
            {   // kv[0] = -cos(kv[0])
                float lo, hi; UNPACK2(lo, hi, p0);
                lo = -__cosf(lo);
                PACK2(p0, lo, hi);
            }
            const bool stop = (tmW[g].x > tendr);
            if (stop) { p0 = 0ull; p1 = 0ull; p2 = 0ull; p3 = 0ull; a8 = 0.f; }
            if (l == 0) {
                ull* kr = kvS + r * 6;
                kr[0] = p0; kr[1] = p1; kr[2] = p2; kr[3] = p3;
                reinterpret_cast<float*>(kr + 4)[0] = a8;
            }
            BAR_ARRIVE(3);                     // kv ready for row warps
        }
    }
}

extern "C" void kernel_launch(void* const* d_in, const int* in_sizes, int n_in,
                              void* d_out, int out_size) {
    const float* ts     = (const float*)d_in[0];
    const float* y0     = (const float*)d_in[1];
    const float* latent = (const float*)d_in[2];
    const int*   length = (const int*)  d_in[3];
    const float* dts    = (const float*)d_in[4];
    const float* dcs    = (const float*)d_in[5];
    const float* W1     = (const float*)d_in[6];
    const float* b1     = (const float*)d_in[7];
    const float* W2     = (const float*)d_in[8];
    const float* b2     = (const float*)d_in[9];
    const float* W3     = (const float*)d_in[10];
    const float* b3     = (const float*)d_in[11];
    float* out = (float*)d_out;

    // floats: 15232 (R14 layout) + kvS 48 + pad 16 = 15296 (61184 B)
    const size_t smem = 15296 * sizeof(float);
    cudaFuncSetAttribute(ode_kernel, cudaFuncAttributeMaxDynamicSharedMemorySize, (int)smem);

    ode_kernel<<<256, NT, smem>>>(ts, y0, latent, length, dts, dcs,
                                  W1, b1, W2, b2, W3, b3, out);
}

// round 16
// speedup vs baseline: 1.4225x; 1.4225x over previous
#include <cuda_runtime.h>
#include <math.h>

#define NT   256
#define BSUB 4
#define TT   128
#define DD   256
#define HW   128

typedef unsigned long long ull;

static __device__ int d_perm[1024];

__device__ __forceinline__ float tanha(float x) {
    float y; asm("tanh.approx.f32 %0, %1;" : "=f"(y) : "f"(x)); return y;
}
#define FFMA2(acc, a, b) \
    asm("fma.rn.f32x2 %0, %1, %2, %3;" : "=l"(acc) : "l"(a), "l"(b), "l"(acc))
#define PACK2(d, lo, hi) \
    asm("mov.b64 %0, {%1,%2};" : "=l"(d) : "f"(lo), "f"(hi))
#define UNPACK2(lo, hi, d) \
    asm("mov.b64 {%0,%1}, %2;" : "=f"(lo), "=f"(hi) : "l"(d))
#define BAR0() asm volatile("bar.sync 0, 256;" ::: "memory")
#define BAR1_SYNC() asm volatile("bar.sync 1, 256;" ::: "memory")
#define BAR1_ARRIVE() asm volatile("bar.arrive 1, 256;" ::: "memory")

__device__ __forceinline__ float interp_c(float t, const float* __restrict__ row) {
    int i = (int)ceilf(t);
    i = i < 1 ? 1 : (i > DD - 1 ? DD - 1 : i);
    float w = t - (float)(i - 1);
    w = fminf(fmaxf(w, 0.f), 1.f);
    return (1.f - w) * row[i - 1] + w * row[i];
}

// Sort row indices by length, descending (LPT: long CTAs first).
__global__ void sort_kernel(const int* __restrict__ length, int B) {
    __shared__ int hist[128];
    __shared__ int base[128];
    int tid = threadIdx.x;
    if (tid < 128) hist[tid] = 0;
    __syncthreads();
    for (int i = tid; i < B; i += blockDim.x) {
        int len = length[i];
        len = len < 0 ? 0 : (len > 127 ? 127 : len);
        atomicAdd(&hist[127 - len], 1);
    }
    __syncthreads();
    if (tid == 0) {
        int acc = 0;
        for (int b = 0; b < 128; ++b) { base[b] = acc; acc += hist[b]; }
    }
    __syncthreads();
    for (int i = tid; i < B; i += blockDim.x) {
        int len = length[i];
        len = len < 0 ? 0 : (len > 127 ? 127 : len);
        int pos = atomicAdd(&base[127 - len], 1);
        d_perm[pos] = i;
    }
}

// L2 partial GEMM over a k-slice of 4*NQ columns, 4 o per thread, 4 rows.
template<int NQ>
__device__ __forceinline__ void l2_slice(
    const ull (*w2p)[2 * NQ],
    const float* __restrict__ h1r, float* __restrict__ pSr,
    int kg, int kbase, int l)
{
    #pragma unroll
    for (int half = 0; half < 2; ++half) {
        ull accA[4] = {0ull, 0ull, 0ull, 0ull};
        ull accB[4] = {0ull, 0ull, 0ull, 0ull};
        const float* ra = h1r + (2 * half) * HW + kbase;
        const float* rb = ra + HW;
        #pragma unroll
        for (int kq = 0; kq < NQ; ++kq) {
            ulonglong2 ha = *reinterpret_cast<const ulonglong2*>(ra + 4 * kq);
            ulonglong2 hb = *reinterpret_cast<const ulonglong2*>(rb + 4 * kq);
            #pragma unroll
            for (int m = 0; m < 4; ++m) {
                FFMA2(accA[m], w2p[m][2 * kq],     ha.x);
                FFMA2(accA[m], w2p[m][2 * kq + 1], ha.y);
                FFMA2(accB[m], w2p[m][2 * kq],     hb.x);
                FFMA2(accB[m], w2p[m][2 * kq + 1], hb.y);
            }
        }
        #pragma unroll
        for (int m = 0; m < 4; ++m) {
            const int o = l + 32 * m;
            float lo, hi;
            UNPACK2(lo, hi, accA[m]);
            pSr[(2 * half) * 1024 + kg * 128 + o] = lo + hi;
            UNPACK2(lo, hi, accB[m]);
            pSr[(2 * half + 1) * 1024 + kg * 128 + o] = lo + hi;
        }
    }
}

__global__ __launch_bounds__(NT, 2)
void ode_kernel(const float* __restrict__ ts, const float* __restrict__ y0,
                const float* __restrict__ latent, const int* __restrict__ length,
                const float* __restrict__ dts, const float* __restrict__ dcs,
                const float* __restrict__ W1, const float* __restrict__ b1,
                const float* __restrict__ W2, const float* __restrict__ b2,
                const float* __restrict__ W3, const float* __restrict__ b3,
                float* __restrict__ out)
{
    extern __shared__ float sm[];
    float* W3t = sm;                      // [128][9]
    float* h1r = W3t + 1152;              // [4][128]
    float* pSr = h1r + 512;               // [4 r][8 kg][128 o]
    float* csS = pSr + 4096;              // [4][256]
    float* tsS = csS + 1024;              // [128]
    float* b2s = tsS + 128;               // [128]
    float* b3s = b2s + 128;               // [12] +4 pad

    __shared__ int prm[BSUB];
    __shared__ int nactS;

    const int tid = threadIdx.x;
    const int l   = tid & 31;
    const int kg  = tid >> 5;
    const int r0  = blockIdx.x * BSUB;

    // ---- perm + active-interval count ----
    if (tid < BSUB) prm[tid] = d_perm[r0 + tid];
    if (tid == 0) {
        int na = 1;
        for (int r = 0; r < BSUB; ++r) {
            int len = length[d_perm[r0 + r]];
            if (len > TT - 1) len = TT - 1;
            if (len > na) na = len;
        }
        nactS = na;
    }
    __syncthreads();

    // ---- one-time setup ----
    for (int i = tid; i < 9 * HW; i += NT) {
        int oo = i >> 7, k = i & 127;
        W3t[k * 9 + oo] = W3[i];
    }
    for (int i = tid; i < BSUB * DD; i += NT) {
        int r = i >> 8;
        csS[i] = dcs[prm[r] * DD + (i & 255)];
    }
    if (tid < TT) tsS[tid] = ts[tid];
    if (tid >= 128) b2s[tid - 128] = b2[tid - 128];
    if (tid < 9)  b3s[tid] = b3[tid];

    // w1v in smem (packed pairs for neuron o = 4*ll+nn) — appended after b3s region
    ull* w1s = reinterpret_cast<ull*>(sm + 7056);   // [20][32]
    for (int i = tid; i < 640; i += NT) {
        int row = i >> 5, ll = i & 31;
        int nn = row / 5, j = row - nn * 5;
        int o = 4 * ll + nn;
        const float* w = W1 + o * 43;
        float lo, hi;
        if (j < 4) { lo = w[2 * j]; hi = w[2 * j + 1]; }
        else       { lo = w[8];     hi = w[41]; }     // (y8, t)
        ull p; PACK2(p, lo, hi);
        w1s[row * 32 + ll] = p;
    }
    const int G = 8 * nactS;   // after first __syncthreads, but read again post-sync below

    if (kg < BSUB) {
        // ================= ROW WARP (warp r = kg) =================
        const int r = kg;
        const int rid = prm[r];
        // L2 slice: 8 k, kbase = 8*kg
        ull w2p[4][4];
        #pragma unroll
        for (int m = 0; m < 4; ++m) {
            const float* wr = W2 + (l + 32 * m) * HW + 8 * kg;
            #pragma unroll
            for (int kp = 0; kp < 4; ++kp) PACK2(w2p[m][kp], wr[2 * kp], wr[2 * kp + 1]);
        }
        ull wcbr[4];                         // (w_c, b1 + W1[:,9:41]·latent[rid])
        #pragma unroll
        for (int nn = 0; nn < 4; ++nn) {
            int o = 4 * l + nn;
            const float* w = W1 + o * 43;
            float bp = b1[o];
            const float* lat = latent + rid * 32;
            #pragma unroll
            for (int j = 0; j < 32; ++j) bp += w[9 + j] * lat[j];
            PACK2(wcbr[nn], w[42], bp);
        }
        // replicated ODE state
        ull ybase[4], yacc[4], ycur[4];
        #pragma unroll
        for (int j = 0; j < 4; ++j) { ybase[j] = 0ull; yacc[j] = 0ull; ycur[j] = 0ull; }
        float ybase8 = 0.f, yacc8 = 0.f, ycur8 = 0.f;
        int len = length[rid];
        int idx = len - 1; if (idx < 0) idx = 0;
        float tendr = ts[idx];
        float y0r = y0[rid];
        if (l == 0) out[rid * TT] = y0r;
        PACK2(ybase[0], y0r, 0.f);
        yacc[0] = ybase[0];
        ycur[0] = ybase[0];
        __syncthreads();

        const int nact = nactS;
        #pragma unroll 1
        for (int g = 0; g < 8 * nact; ++g) {
            const int n = g >> 3, sub = (g >> 2) & 1, s = g & 3;
            float t0v = tsS[n];
            float dtf = (tsS[n + 1] - t0v) * 0.5f;
            float tstart = t0v + (sub ? dtf : 0.f);
            float As = (s == 0) ? 0.f : ((s == 3) ? 1.f : 0.5f);
            float tt = tstart + As * dtf;

            // ---- layer 1: 4 neurons/lane ----
            {
                float c = interp_c(tt, csS + r * DD);
                ull ytt, c1;
                PACK2(ytt, ycur8, tt);
                PACK2(c1, c, 1.0f);
                float hq[4];
                #pragma unroll
                for (int nn = 0; nn < 4; ++nn) {
                    const ull* wb = w1s + (nn * 5) * 32 + l;
                    ull acc = 0ull;
                    FFMA2(acc, wb[0],       ycur[0]);
                    FFMA2(acc, wb[32],      ycur[1]);
                    FFMA2(acc, wb[64],      ycur[2]);
                    FFMA2(acc, wb[96],      ycur[3]);
                    FFMA2(acc, wb[128],     ytt);
                    FFMA2(acc, wcbr[nn],    c1);
                    float lo, hi; UNPACK2(lo, hi, acc);
                    hq[nn] = tanha(lo + hi);
                }
                *reinterpret_cast<float4*>(h1r + r * HW + 4 * l) =
                    make_float4(hq[0], hq[1], hq[2], hq[3]);
            }
            BAR0();

            l2_slice<2>(w2p, h1r, pSr, kg, 8 * kg, l);
            BAR1_SYNC();

            // ---- layer 3 + epilogue ----
            {
                float acc9[9];
                #pragma unroll
                for (int o2 = 0; o2 < 9; ++o2) acc9[o2] = 0.f;
                const float* pb = pSr + r * 1024;
                #pragma unroll
                for (int j = 0; j < 4; ++j) {
                    const int o = 32 * j + l;
                    float p0 = pb[o]       + pb[128 + o];
                    float p1 = pb[256 + o] + pb[384 + o];
                    float p2 = pb[512 + o] + pb[640 + o];
                    float p3 = pb[768 + o] + pb[896 + o];
                    float v = ((p0 + p1) + (p2 + p3)) + b2s[o];
                    float hh = tanha(v);
                    const float* wk = W3t + o * 9;
                    #pragma unroll
                    for (int o2 = 0; o2 < 9; ++o2)
                        acc9[o2] += hh * wk[o2];
                }
                #pragma unroll
                for (int off = 16; off > 0; off >>= 1) {
                    #pragma unroll
                    for (int o2 = 0; o2 < 9; ++o2)
                        acc9[o2] += __shfl_xor_sync(0xffffffffu, acc9[o2], off);
                }
                bool stop = (tt > tendr);
                float kv[9];
                #pragma unroll
                for (int o2 = 0; o2 < 9; ++o2) {
                    float a = acc9[o2] + b3s[o2];
                    if (o2 == 0) a = -__cosf(a);
                    kv[o2] = stop ? 0.f : a;
                }
                float wgt = dtf * (1.f / 6.f) * ((s == 0 || s == 3) ? 1.f : 2.f);
                ull k01, k23, k45, k67, wg2;
                PACK2(k01, kv[0], kv[1]);
                PACK2(k23, kv[2], kv[3]);
                PACK2(k45, kv[4], kv[5]);
                PACK2(k67, kv[6], kv[7]);
                PACK2(wg2, wgt, wgt);
                FFMA2(yacc[0], wg2, k01);
                FFMA2(yacc[1], wg2, k23);
                FFMA2(yacc[2], wg2, k45);
                FFMA2(yacc[3], wg2, k67);
                yacc8 = fmaf(wgt, kv[8], yacc8);
                if (s < 3) {
                    float stg = ((s == 2) ? 1.f : 0.5f) * dtf;
                    ull st2; PACK2(st2, stg, stg);
                    ycur[0] = ybase[0]; FFMA2(ycur[0], st2, k01);
                    ycur[1] = ybase[1]; FFMA2(ycur[1], st2, k23);
                    ycur[2] = ybase[2]; FFMA2(ycur[2], st2, k45);
                    ycur[3] = ybase[3]; FFMA2(ycur[3], st2, k67);
                    ycur8 = fmaf(stg, kv[8], ybase8);
                } else {
                    #pragma unroll
                    for (int j = 0; j < 4; ++j) { ybase[j] = yacc[j]; ycur[j] = yacc[j]; }
                    ybase8 = yacc8; ycur8 = yacc8;
                    if (sub == 1 && l == 0) {
                        float yb, dum; UNPACK2(yb, dum, ybase[0]);
                        out[rid * TT + n + 1] = yb;
                    }
                }
            }
        }

        // ---- fill frozen tail: out[n] for n in [nact+1, TT) ----
        {
            float yb, dum; UNPACK2(yb, dum, ybase[0]);
            for (int n = nact + 1 + l; n < TT; n += 32)
                out[rid * TT + n] = yb;
        }
    } else {
        // ================= HELPER WARP (kg 4..7): 24-k slice =================
        const int kbase = 32 + 24 * (kg - 4);
        ull w2p[4][12];
        #pragma unroll
        for (int m = 0; m < 4; ++m) {
            const float* wr = W2 + (l + 32 * m) * HW + kbase;
            #pragma unroll
            for (int kp = 0; kp < 12; ++kp) PACK2(w2p[m][kp], wr[2 * kp], wr[2 * kp + 1]);
        }
        __syncthreads();
        const int Gh = 8 * nactS;
        #pragma unroll 1
        for (int g = 0; g < Gh; ++g) {
            BAR0();
            l2_slice<6>(w2p, h1r, pSr, kg, kbase, l);
            BAR1_ARRIVE();
        }
    }
}

extern "C" void kernel_launch(void* const* d_in, const int* in_sizes, int n_in,
                              void* d_out, int out_size) {
    const float* ts     = (const float*)d_in[0];
    const float* y0     = (const float*)d_in[1];
    const float* latent = (const float*)d_in[2];
    const int*   length = (const int*)  d_in[3];
    const float* dts    = (const float*)d_in[4];
    const float* dcs    = (const float*)d_in[5];
    const float* W1     = (const float*)d_in[6];
    const float* b1     = (const float*)d_in[7];
    const float* W2     = (const float*)d_in[8];
    const float* b2     = (const float*)d_in[9];
    const float* W3     = (const float*)d_in[10];
    const float* b3     = (const float*)d_in[11];
    float* out = (float*)d_out;
    const int B = in_sizes[3];

    sort_kernel<<<1, 256>>>(length, B);

    // floats: W3t 1152 + h1r 512 + pSr 4096 + csS 1024 + tsS 128 + b2s 128
    //         + b3s 16 = 7056, then w1s 1280 -> 8336 (33344 B)
    const size_t smem = 8336 * sizeof(float);
    cudaFuncSetAttribute(ode_kernel, cudaFuncAttributeMaxDynamicSharedMemorySize, (int)smem);

    ode_kernel<<<256, NT, smem>>>(ts, y0, latent, length, dts, dcs,
                                  W1, b1, W2, b2, W3, b3, out);
}

// round 17
// speedup vs baseline: 1.6708x; 1.1746x over previous
#include <cuda_runtime.h>
#include <math.h>

#define NT   256
#define BSUB 4
#define TT   128
#define DD   256
#define HW   128

typedef unsigned long long ull;

static __device__ int d_perm[1024];

__device__ __forceinline__ float tanha(float x) {
    float y; asm("tanh.approx.f32 %0, %1;" : "=f"(y) : "f"(x)); return y;
}
#define FFMA2(acc, a, b) \
    asm("fma.rn.f32x2 %0, %1, %2, %3;" : "=l"(acc) : "l"(a), "l"(b), "l"(acc))
#define PACK2(d, lo, hi) \
    asm("mov.b64 %0, {%1,%2};" : "=l"(d) : "f"(lo), "f"(hi))
#define UNPACK2(lo, hi, d) \
    asm("mov.b64 {%0,%1}, %2;" : "=f"(lo), "=f"(hi) : "l"(d))
#define BAR0() asm volatile("bar.sync 0, 256;" ::: "memory")
#define BAR1_SYNC() asm volatile("bar.sync 1, 256;" ::: "memory")
#define BAR1_ARRIVE() asm volatile("bar.arrive 1, 256;" ::: "memory")

__device__ __forceinline__ float interp_c(float t, const float* __restrict__ row) {
    int i = (int)ceilf(t);
    i = i < 1 ? 1 : (i > DD - 1 ? DD - 1 : i);
    float w = t - (float)(i - 1);
    w = fminf(fmaxf(w, 0.f), 1.f);
    return (1.f - w) * row[i - 1] + w * row[i];
}

// Sort row indices by length, descending.
__global__ void sort_kernel(const int* __restrict__ length, int B) {
    __shared__ int hist[128];
    __shared__ int base[128];
    int tid = threadIdx.x;
    if (tid < 128) hist[tid] = 0;
    __syncthreads();
    for (int i = tid; i < B; i += blockDim.x) {
        int len = length[i];
        len = len < 0 ? 0 : (len > 127 ? 127 : len);
        atomicAdd(&hist[127 - len], 1);
    }
    __syncthreads();
    if (tid == 0) {
        int acc = 0;
        for (int b = 0; b < 128; ++b) { base[b] = acc; acc += hist[b]; }
    }
    __syncthreads();
    for (int i = tid; i < B; i += blockDim.x) {
        int len = length[i];
        len = len < 0 ? 0 : (len > 127 ? 127 : len);
        int pos = atomicAdd(&base[127 - len], 1);
        d_perm[pos] = i;
    }
}

// L2 partial GEMM over a k-slice of 4*NQ columns, 4 o per thread, 4 rows.
template<int NQ>
__device__ __forceinline__ void l2_slice(
    const ull (*w2p)[2 * NQ],
    const float* __restrict__ h1r, float* __restrict__ pSr,
    int kg, int kbase, int l)
{
    #pragma unroll
    for (int half = 0; half < 2; ++half) {
        ull accA[4] = {0ull, 0ull, 0ull, 0ull};
        ull accB[4] = {0ull, 0ull, 0ull, 0ull};
        const float* ra = h1r + (2 * half) * HW + kbase;
        const float* rb = ra + HW;
        #pragma unroll
        for (int kq = 0; kq < NQ; ++kq) {
            ulonglong2 ha = *reinterpret_cast<const ulonglong2*>(ra + 4 * kq);
            ulonglong2 hb = *reinterpret_cast<const ulonglong2*>(rb + 4 * kq);
            #pragma unroll
            for (int m = 0; m < 4; ++m) {
                FFMA2(accA[m], w2p[m][2 * kq],     ha.x);
                FFMA2(accA[m], w2p[m][2 * kq + 1], ha.y);
                FFMA2(accB[m], w2p[m][2 * kq],     hb.x);
                FFMA2(accB[m], w2p[m][2 * kq + 1], hb.y);
            }
        }
        #pragma unroll
        for (int m = 0; m < 4; ++m) {
            const int o = l + 32 * m;
            float lo, hi;
            UNPACK2(lo, hi, accA[m]);
            pSr[(2 * half) * 1024 + kg * 128 + o] = lo + hi;
            UNPACK2(lo, hi, accB[m]);
            pSr[(2 * half + 1) * 1024 + kg * 128 + o] = lo + hi;
        }
    }
}

__global__ __launch_bounds__(NT, 2)
void ode_kernel(const float* __restrict__ ts, const float* __restrict__ y0,
                const float* __restrict__ latent, const int* __restrict__ length,
                const float* __restrict__ dts, const float* __restrict__ dcs,
                const float* __restrict__ W1, const float* __restrict__ b1,
                const float* __restrict__ W2, const float* __restrict__ b2,
                const float* __restrict__ W3, const float* __restrict__ b3,
                float* __restrict__ out)
{
    extern __shared__ float sm[];
    float* W3t = sm;                      // [128][9]
    float* h1r = W3t + 1152;              // [4][128]
    float* pSr = h1r + 512;               // [4 r][8 kg][128 o]
    float* csS = pSr + 4096;              // [4][256]
    float* tsS = csS + 1024;              // [128]
    float* b2s = tsS + 128;               // [128]
    float* b3s = b2s + 128;               // [12] +4 pad

    __shared__ int prm[BSUB];
    __shared__ int nactS;

    const int tid = threadIdx.x;
    const int l   = tid & 31;
    const int kg  = tid >> 5;
    // bid->group remap: bids b and b+148 share an SM; pair longest with shortest.
    const int gb  = (blockIdx.x < 148) ? (int)blockIdx.x : (403 - (int)blockIdx.x);
    const int r0  = gb * BSUB;

    // ---- perm + active-interval count ----
    if (tid < BSUB) prm[tid] = d_perm[r0 + tid];
    if (tid == 0) {
        int na = 1;
        for (int r = 0; r < BSUB; ++r) {
            int len = length[d_perm[r0 + r]];
            if (len > TT - 1) len = TT - 1;
            if (len > na) na = len;
        }
        nactS = na;
    }
    __syncthreads();

    // ---- one-time setup ----
    for (int i = tid; i < 9 * HW; i += NT) {
        int oo = i >> 7, k = i & 127;
        W3t[k * 9 + oo] = W3[i];
    }
    for (int i = tid; i < BSUB * DD; i += NT) {
        int r = i >> 8;
        csS[i] = dcs[prm[r] * DD + (i & 255)];
    }
    if (tid < TT) tsS[tid] = ts[tid];
    if (tid >= 128) b2s[tid - 128] = b2[tid - 128];
    if (tid < 9)  b3s[tid] = b3[tid];

    ull* w1s = reinterpret_cast<ull*>(sm + 7056);   // [20][32]
    for (int i = tid; i < 640; i += NT) {
        int row = i >> 5, ll = i & 31;
        int nn = row / 5, j = row - nn * 5;
        int o = 4 * ll + nn;
        const float* w = W1 + o * 43;
        float lo, hi;
        if (j < 4) { lo = w[2 * j]; hi = w[2 * j + 1]; }
        else       { lo = w[8];     hi = w[41]; }     // (y8, t)
        ull p; PACK2(p, lo, hi);
        w1s[row * 32 + ll] = p;
    }

    if (kg < BSUB) {
        // ================= ROW WARP (warp r = kg) =================
        const int r = kg;
        const int rid = prm[r];
        ull w2p[4][4];                       // 8-k slice, kbase = 8*kg
        #pragma unroll
        for (int m = 0; m < 4; ++m) {
            const float* wr = W2 + (l + 32 * m) * HW + 8 * kg;
            #pragma unroll
            for (int kp = 0; kp < 4; ++kp) PACK2(w2p[m][kp], wr[2 * kp], wr[2 * kp + 1]);
        }
        ull wcbr[4];                         // (w_c, b1 + W1[:,9:41]·latent[rid])
        #pragma unroll
        for (int nn = 0; nn < 4; ++nn) {
            int o = 4 * l + nn;
            const float* w = W1 + o * 43;
            float bp = b1[o];
            const float* lat = latent + rid * 32;
            #pragma unroll
            for (int j = 0; j < 32; ++j) bp += w[9 + j] * lat[j];
            PACK2(wcbr[nn], w[42], bp);
        }
        ull ybase[4], yacc[4], ycur[4];
        #pragma unroll
        for (int j = 0; j < 4; ++j) { ybase[j] = 0ull; yacc[j] = 0ull; ycur[j] = 0ull; }
        float ybase8 = 0.f, yacc8 = 0.f, ycur8 = 0.f;
        int len = length[rid];
        int idx = len - 1; if (idx < 0) idx = 0;
        float tendr = ts[idx];
        float y0r = y0[rid];
        if (l == 0) out[rid * TT] = y0r;
        PACK2(ybase[0], y0r, 0.f);
        yacc[0] = ybase[0];
        ycur[0] = ybase[0];
        __syncthreads();

        const int nact = nactS;
        #pragma unroll 1
        for (int g = 0; g < 8 * nact; ++g) {
            const int n = g >> 3, sub = (g >> 2) & 1, s = g & 3;
            float t0v = tsS[n];
            float dtf = (tsS[n + 1] - t0v) * 0.5f;
            float tstart = t0v + (sub ? dtf : 0.f);
            float As = (s == 0) ? 0.f : ((s == 3) ? 1.f : 0.5f);
            float tt = tstart + As * dtf;

            // ---- layer 1: 4 neurons/lane ----
            {
                float c = interp_c(tt, csS + r * DD);
                ull ytt, c1;
                PACK2(ytt, ycur8, tt);
                PACK2(c1, c, 1.0f);
                float hq[4];
                #pragma unroll
                for (int nn = 0; nn < 4; ++nn) {
                    const ull* wb = w1s + (nn * 5) * 32 + l;
                    ull acc = 0ull;
                    FFMA2(acc, wb[0],       ycur[0]);
                    FFMA2(acc, wb[32],      ycur[1]);
                    FFMA2(acc, wb[64],      ycur[2]);
                    FFMA2(acc, wb[96],      ycur[3]);
                    FFMA2(acc, wb[128],     ytt);
                    FFMA2(acc, wcbr[nn],    c1);
                    float lo, hi; UNPACK2(lo, hi, acc);
                    hq[nn] = tanha(lo + hi);
                }
                *reinterpret_cast<float4*>(h1r + r * HW + 4 * l) =
                    make_float4(hq[0], hq[1], hq[2], hq[3]);
            }
            BAR0();

            l2_slice<2>(w2p, h1r, pSr, kg, 8 * kg, l);
            BAR1_SYNC();

            // ---- layer 3 + epilogue ----
            {
                float acc9[9];
                #pragma unroll
                for (int o2 = 0; o2 < 9; ++o2) acc9[o2] = 0.f;
                const float* pb = pSr + r * 1024;
                #pragma unroll
                for (int j = 0; j < 4; ++j) {
                    const int o = 32 * j + l;
                    float p0 = pb[o]       + pb[128 + o];
                    float p1 = pb[256 + o] + pb[384 + o];
                    float p2 = pb[512 + o] + pb[640 + o];
                    float p3 = pb[768 + o] + pb[896 + o];
                    float v = ((p0 + p1) + (p2 + p3)) + b2s[o];
                    float hh = tanha(v);
                    const float* wk = W3t + o * 9;
                    #pragma unroll
                    for (int o2 = 0; o2 < 9; ++o2)
                        acc9[o2] += hh * wk[o2];
                }
                #pragma unroll
                for (int off = 16; off > 0; off >>= 1) {
                    #pragma unroll
                    for (int o2 = 0; o2 < 9; ++o2)
                        acc9[o2] += __shfl_xor_sync(0xffffffffu, acc9[o2], off);
                }
                bool stop = (tt > tendr);
                float kv[9];
                #pragma unroll
                for (int o2 = 0; o2 < 9; ++o2) {
                    float a = acc9[o2] + b3s[o2];
                    if (o2 == 0) a = -__cosf(a);
                    kv[o2] = stop ? 0.f : a;
                }
                float wgt = dtf * (1.f / 6.f) * ((s == 0 || s == 3) ? 1.f : 2.f);
                ull k01, k23, k45, k67, wg2;
                PACK2(k01, kv[0], kv[1]);
                PACK2(k23, kv[2], kv[3]);
                PACK2(k45, kv[4], kv[5]);
                PACK2(k67, kv[6], kv[7]);
                PACK2(wg2, wgt, wgt);
                FFMA2(yacc[0], wg2, k01);
                FFMA2(yacc[1], wg2, k23);
                FFMA2(yacc[2], wg2, k45);
                FFMA2(yacc[3], wg2, k67);
                yacc8 = fmaf(wgt, kv[8], yacc8);
                if (s < 3) {
                    float stg = ((s == 2) ? 1.f : 0.5f) * dtf;
                    ull st2; PACK2(st2, stg, stg);
                    ycur[0] = ybase[0]; FFMA2(ycur[0], st2, k01);
                    ycur[1] = ybase[1]; FFMA2(ycur[1], st2, k23);
                    ycur[2] = ybase[2]; FFMA2(ycur[2], st2, k45);
                    ycur[3] = ybase[3]; FFMA2(ycur[3], st2, k67);
                    ycur8 = fmaf(stg, kv[8], ybase8);
                } else {
                    #pragma unroll
                    for (int j = 0; j < 4; ++j) { ybase[j] = yacc[j]; ycur[j] = yacc[j]; }
                    ybase8 = yacc8; ycur8 = yacc8;
                    if (sub == 1 && l == 0) {
                        float yb, dum; UNPACK2(yb, dum, ybase[0]);
                        out[rid * TT + n + 1] = yb;
                    }
                }
            }
        }

        // ---- fill frozen tail ----
        {
            float yb, dum; UNPACK2(yb, dum, ybase[0]);
            for (int n = nact + 1 + l; n < TT; n += 32)
                out[rid * TT + n] = yb;
        }
    } else {
        // ================= HELPER WARP (kg 4..7): 24-k slice =================
        const int kbase = 32 + 24 * (kg - 4);
        ull w2p[4][12];
        #pragma unroll
        for (int m = 0; m < 4; ++m) {
            const float* wr = W2 + (l + 32 * m) * HW + kbase;
            #pragma unroll
            for (int kp = 0; kp < 12; ++kp) PACK2(w2p[m][kp], wr[2 * kp], wr[2 * kp + 1]);
        }
        __syncthreads();
        const int Gh = 8 * nactS;
        #pragma unroll 1
        for (int g = 0; g < Gh; ++g) {
            BAR0();
            l2_slice<6>(w2p, h1r, pSr, kg, kbase, l);
            BAR1_ARRIVE();
        }
    }
}

extern "C" void kernel_launch(void* const* d_in, const int* in_sizes, int n_in,
                              void* d_out, int out_size) {
    const float* ts     = (const float*)d_in[0];
    const float* y0     = (const float*)d_in[1];
    const float* latent = (const float*)d_in[2];
    const int*   length = (const int*)  d_in[3];
    const float* dts    = (const float*)d_in[4];
    const float* dcs    = (const float*)d_in[5];
    const float* W1     = (const float*)d_in[6];
    const float* b1     = (const float*)d_in[7];
    const float* W2     = (const float*)d_in[8];
    const float* b2     = (const float*)d_in[9];
    const float* W3     = (const float*)d_in[10];
    const float* b3     = (const float*)d_in[11];
    float* out = (float*)d_out;
    const int B = in_sizes[3];

    sort_kernel<<<1, 256>>>(length, B);

    const size_t smem = 8336 * sizeof(float);   // 33344 B
    cudaFuncSetAttribute(ode_kernel, cudaFuncAttributeMaxDynamicSharedMemorySize, (int)smem);

    ode_kernel<<<256, NT, smem>>>(ts, y0, latent, length, dts, dcs,
                                  W1, b1, W2, b2, W3, b3, out);
}